// round 6
// baseline (speedup 1.0000x reference)
#include <cuda_runtime.h>
#include <cstdint>

#define KDIM 512
#define FDIM 512
#define BM   128
#define BN   32                 // N-chunk per iteration (16 chunks)

// smem layout (bytes)
#define SM_X    0               // 128 x 512 int8, XOR-swizzled rows
#define SM_W    65536           // 2 x (32 x 512) int8 double buffer
#define SM_INV  98304           // 512 floats
#define SM_BIAS 100352          // 512 floats
#define SMEM_TOTAL 102400       // 100 KB -> 2 CTAs/SM

#define WBUF_BYTES (BN * KDIM)  // 16384

__device__ __align__(16) int8_t g_wq[FDIM * KDIM];   // [F][K]
__device__ float g_inv[FDIM];

__device__ __forceinline__ uint32_t smem_u32(const void* p) {
    uint32_t a;
    asm("{ .reg .u64 t; cvta.to.shared.u64 t, %1; cvt.u32.u64 %0, t; }" : "=r"(a) : "l"(p));
    return a;
}
__device__ __forceinline__ void cp_async16(uint32_t dst, const void* src) {
    asm volatile("cp.async.cg.shared.global [%0], [%1], 16;" :: "r"(dst), "l"(src));
}
__device__ __forceinline__ void ldsm_x4(uint32_t addr, unsigned& r0, unsigned& r1,
                                        unsigned& r2, unsigned& r3) {
    asm volatile("ldmatrix.sync.aligned.m8n8.x4.shared.b16 {%0,%1,%2,%3}, [%4];"
                 : "=r"(r0), "=r"(r1), "=r"(r2), "=r"(r3) : "r"(addr));
}

// ---------------------------------------------------------------------------
// Weight prequant: 32 blocks x 256 threads, 16 output-cols per block.
// ---------------------------------------------------------------------------
__global__ void quant_w_kernel(const float* __restrict__ kernel) {
    __shared__ float sm[512 * 17];
    __shared__ float red[16][16];
    __shared__ float sscale[16];
    const int j0 = blockIdx.x * 16;
    const int t  = threadIdx.x;

    #pragma unroll 4
    for (int i = 0; i < 32; ++i) {
        int idx = i * 256 + t;
        int k = idx >> 4, c = idx & 15;
        sm[k * 17 + c] = kernel[k * FDIM + j0 + c];
    }
    __syncthreads();
    {
        int c = t & 15, kr = t >> 4;
        float m = 0.f;
        #pragma unroll 8
        for (int i = 0; i < 32; ++i)
            m = fmaxf(m, fabsf(sm[(kr + i * 16) * 17 + c]));
        red[kr][c] = m;
    }
    __syncthreads();
    if (t < 16) {
        float m = red[0][t];
        #pragma unroll
        for (int r = 1; r < 16; ++r) m = fmaxf(m, red[r][t]);
        float s = __fdiv_rn(127.0f, fmaxf(m, 1e-7f));
        sscale[t] = s;
        const float A_SCALE = 127.0f / 3.0f;
        g_inv[j0 + t] = __fdiv_rn(1.0f, __fmul_rn(A_SCALE, s));
    }
    __syncthreads();

    const int w = t >> 5, lane = t & 31;
    #pragma unroll
    for (int cc = 0; cc < 2; ++cc) {
        int c = w * 2 + cc;
        float s = sscale[c];
        int kb = lane * 16;
        unsigned pk[4];
        #pragma unroll
        for (int i = 0; i < 4; ++i) {
            int q[4];
            #pragma unroll
            for (int jj = 0; jj < 4; ++jj) {
                float v = __fmul_rn(sm[(kb + i * 4 + jj) * 17 + c], s);
                int qi = __float2int_rn(v);
                q[jj] = max(-127, min(127, qi));
            }
            pk[i] = (q[0] & 0xff) | ((q[1] & 0xff) << 8) |
                    ((q[2] & 0xff) << 16) | ((unsigned)(q[3] & 0xff) << 24);
        }
        *(int4*)&g_wq[(size_t)(j0 + c) * KDIM + kb] =
            make_int4(pk[0], pk[1], pk[2], pk[3]);
    }
}

// ---------------------------------------------------------------------------
// Fused quantize-x + int8 legacy-MMA GEMM, ldmatrix fragment loads,
// 2 CTAs/SM, double-buffered W via cp.async.
// ---------------------------------------------------------------------------
__device__ __forceinline__ void load_w_async(uint32_t buf_u, int nb, int t) {
    const int8_t* base = g_wq + (size_t)nb * BN * KDIM;
    #pragma unroll
    for (int i = 0; i < 4; ++i) {
        int idx = i * 256 + t;               // 1024 16B-chunks
        int n = idx >> 5, c16 = idx & 31;
        uint32_t dst = buf_u + n * KDIM + ((c16 * 16) ^ ((n & 7) << 4));
        cp_async16(dst, base + n * KDIM + c16 * 16);
    }
    asm volatile("cp.async.commit_group;" ::: "memory");
}

__global__ void __launch_bounds__(256, 2)
gemm_kernel(const float* __restrict__ x, const float* __restrict__ bias,
            float* __restrict__ y) {
    extern __shared__ char smem[];
    int8_t* xs = (int8_t*)(smem + SM_X);
    int8_t* ws = (int8_t*)(smem + SM_W);
    float* sinv  = (float*)(smem + SM_INV);
    float* sbias = (float*)(smem + SM_BIAS);

    const int t  = threadIdx.x;
    const int r0 = blockIdx.x * BM;
    const uint32_t xs_u = smem_u32(xs);
    const uint32_t ws_u = smem_u32(ws);

    // W chunk 0 first: overlaps the x-quant phase
    load_w_async(ws_u, 0, t);

    for (int i = t; i < FDIM; i += 256) {
        sinv[i]  = g_inv[i];
        sbias[i] = bias[i];
    }

    // quantize x tile: 128 x 512 fp32 -> int8, XOR-swizzled rows
    const float A_SCALE = 127.0f / 3.0f;
    #pragma unroll 4
    for (int i = 0; i < 16; ++i) {
        int idx = i * 256 + t;               // 16B-chunk id (4096 total)
        int row = idx >> 5, c16 = idx & 31;
        const float4* src = (const float4*)(x + (size_t)(r0 + row) * KDIM + c16 * 16);
        float4 v0 = __ldg(src), v1 = __ldg(src + 1), v2 = __ldg(src + 2), v3 = __ldg(src + 3);
        int pk[4];
        float4 vv[4] = {v0, v1, v2, v3};
        #pragma unroll
        for (int j = 0; j < 4; ++j) {
            int q0 = max(-127, min(127, __float2int_rn(__fmul_rn(vv[j].x, A_SCALE))));
            int q1 = max(-127, min(127, __float2int_rn(__fmul_rn(vv[j].y, A_SCALE))));
            int q2 = max(-127, min(127, __float2int_rn(__fmul_rn(vv[j].z, A_SCALE))));
            int q3 = max(-127, min(127, __float2int_rn(__fmul_rn(vv[j].w, A_SCALE))));
            pk[j] = (q0 & 0xff) | ((q1 & 0xff) << 8) |
                    ((q2 & 0xff) << 16) | ((unsigned)(q3 & 0xff) << 24);
        }
        *(int4*)&xs[row * KDIM + ((c16 * 16) ^ ((row & 7) << 4))] =
            make_int4(pk[0], pk[1], pk[2], pk[3]);
    }

    const int warp = t >> 5, lane = t & 31;
    const int wm = warp >> 1, wn = warp & 1;     // 4 M-warps x 2 N-warps
    const int grp = lane >> 2, qid = lane & 3;

    // ldmatrix lane -> (matrix id, row-within-matrix)
    const int mid  = lane >> 3;                  // 0..3
    const int mrow = lane & 7;                   // 0..7
    const int bsel = (mid >> 1) << 4;            // 0 or 16 (16B half select)
    const uint32_t gxor = (uint32_t)mrow << 4;   // row-swizzle XOR term

    // A: matrices {rows 0-7, rows 8-15} x {bytes 0-15, 16-31} of a 16x32 tile
    const uint32_t a_row0 = wm * 32 + (mid & 1) * 8 + mrow;      // mt=0
    const uint32_t aA0 = xs_u + a_row0 * KDIM;                   // + per-ks offset
    const uint32_t aA1 = aA0 + 16 * KDIM;                        // mt=1
    // B: 16 n-rows (both nt) x 32 k-bytes
    const uint32_t b_row = wn * 16 + (mid & 1) * 8 + mrow;
    const uint32_t bB0 = ws_u + b_row * KDIM;

    float* yr0 = y + (size_t)(r0 + wm * 32 + grp) * FDIM;

    for (int nb = 0; nb < 16; ++nb) {
        asm volatile("cp.async.wait_group 0;" ::: "memory");
        __syncthreads();
        if (nb < 15) load_w_async(ws_u + ((nb + 1) & 1) * WBUF_BYTES, nb + 1, t);

        const uint32_t bbase = bB0 + (nb & 1) * WBUF_BYTES;

        int acc[2][2][4];
        #pragma unroll
        for (int mt = 0; mt < 2; ++mt)
            #pragma unroll
            for (int nt = 0; nt < 2; ++nt)
                #pragma unroll
                for (int r = 0; r < 4; ++r) acc[mt][nt][r] = 0;

        #pragma unroll
        for (int ks = 0; ks < 16; ++ks) {
            const uint32_t off = (uint32_t)(ks * 32 + bsel) ^ gxor;
            unsigned a[2][4], bb[4];
            ldsm_x4(aA0 + off, a[0][0], a[0][1], a[0][2], a[0][3]);
            ldsm_x4(aA1 + off, a[1][0], a[1][1], a[1][2], a[1][3]);
            // bb = {b[0][0], b[1][0], b[0][1], b[1][1]}
            ldsm_x4(bbase + off, bb[0], bb[1], bb[2], bb[3]);
            #pragma unroll
            for (int mt = 0; mt < 2; ++mt) {
                asm volatile(
                    "mma.sync.aligned.m16n8k32.row.col.s32.s8.s8.s32 "
                    "{%0,%1,%2,%3},{%4,%5,%6,%7},{%8,%9},{%0,%1,%2,%3};\n"
                    : "+r"(acc[mt][0][0]), "+r"(acc[mt][0][1]),
                      "+r"(acc[mt][0][2]), "+r"(acc[mt][0][3])
                    : "r"(a[mt][0]), "r"(a[mt][1]), "r"(a[mt][2]), "r"(a[mt][3]),
                      "r"(bb[0]), "r"(bb[2]));
                asm volatile(
                    "mma.sync.aligned.m16n8k32.row.col.s32.s8.s8.s32 "
                    "{%0,%1,%2,%3},{%4,%5,%6,%7},{%8,%9},{%0,%1,%2,%3};\n"
                    : "+r"(acc[mt][1][0]), "+r"(acc[mt][1][1]),
                      "+r"(acc[mt][1][2]), "+r"(acc[mt][1][3])
                    : "r"(a[mt][0]), "r"(a[mt][1]), "r"(a[mt][2]), "r"(a[mt][3]),
                      "r"(bb[1]), "r"(bb[3]));
            }
        }

        // epilogue: dequant + bias, float2 stores
        #pragma unroll
        for (int mt = 0; mt < 2; ++mt) {
            float* yr = yr0 + mt * 16 * FDIM;
            #pragma unroll
            for (int nt = 0; nt < 2; ++nt) {
                int col = nb * BN + wn * 16 + nt * 8 + qid * 2;
                float i0 = sinv[col], i1 = sinv[col + 1];
                float b0 = sbias[col], b1 = sbias[col + 1];
                float2 v0, v1;
                v0.x = (float)acc[mt][nt][0] * i0 + b0;
                v0.y = (float)acc[mt][nt][1] * i1 + b1;
                v1.x = (float)acc[mt][nt][2] * i0 + b0;
                v1.y = (float)acc[mt][nt][3] * i1 + b1;
                *(float2*)(yr + col) = v0;
                *(float2*)(yr + 8 * FDIM + col) = v1;
            }
        }
    }
}

// ---------------------------------------------------------------------------
extern "C" void kernel_launch(void* const* d_in, const int* in_sizes, int n_in,
                              void* d_out, int out_size) {
    const float* x    = (const float*)d_in[0];
    const float* kern = (const float*)d_in[1];
    const float* bias = (const float*)d_in[2];
    float* y = (float*)d_out;
    const int nrows = in_sizes[0] / KDIM;

    cudaFuncSetAttribute(gemm_kernel,
                         cudaFuncAttributeMaxDynamicSharedMemorySize, SMEM_TOTAL);

    quant_w_kernel<<<FDIM / 16, 256>>>(kern);
    gemm_kernel<<<nrows / BM, 256, SMEM_TOTAL>>>(x, bias, y);
}

// round 8
// speedup vs baseline: 1.0275x; 1.0275x over previous
#include <cuda_runtime.h>
#include <cstdint>

#define KDIM 512
#define FDIM 512
#define BM   64
#define BN   32                 // 16 chunks per tile
#define NTILES 1024
#define GRID 444                // 3 CTAs x 148 SMs

// smem layout (bytes)
#define SM_X    0               // 64 x 512 int8, XOR-swizzled rows
#define SM_W    32768           // 2 x (32 x 512) int8 double buffer
#define SM_INV  65536           // 512 floats
#define SM_BIAS 67584           // 512 floats
#define SMEM_TOTAL 69632        // 68 KB -> 3 CTAs/SM

#define WBUF_BYTES (BN * KDIM)  // 16384

__device__ __align__(16) int8_t g_wq[FDIM * KDIM];   // [F][K]
__device__ float g_inv[FDIM];

__device__ __forceinline__ uint32_t smem_u32(const void* p) {
    uint32_t a;
    asm("{ .reg .u64 t; cvta.to.shared.u64 t, %1; cvt.u32.u64 %0, t; }" : "=r"(a) : "l"(p));
    return a;
}
__device__ __forceinline__ void cp_async16(uint32_t dst, const void* src) {
    asm volatile("cp.async.cg.shared.global [%0], [%1], 16;" :: "r"(dst), "l"(src));
}
__device__ __forceinline__ void ldsm_x4(uint32_t addr, unsigned& r0, unsigned& r1,
                                        unsigned& r2, unsigned& r3) {
    asm volatile("ldmatrix.sync.aligned.m8n8.x4.shared.b16 {%0,%1,%2,%3}, [%4];"
                 : "=r"(r0), "=r"(r1), "=r"(r2), "=r"(r3) : "r"(addr));
}

// ---------------------------------------------------------------------------
// Weight prequant: 32 blocks x 256 threads, 16 output-cols per block.
// ---------------------------------------------------------------------------
__global__ void quant_w_kernel(const float* __restrict__ kernel) {
    __shared__ float sm[512 * 17];
    __shared__ float red[16][16];
    __shared__ float sscale[16];
    const int j0 = blockIdx.x * 16;
    const int t  = threadIdx.x;

    #pragma unroll 4
    for (int i = 0; i < 32; ++i) {
        int idx = i * 256 + t;
        int k = idx >> 4, c = idx & 15;
        sm[k * 17 + c] = kernel[k * FDIM + j0 + c];
    }
    __syncthreads();
    {
        int c = t & 15, kr = t >> 4;
        float m = 0.f;
        #pragma unroll 8
        for (int i = 0; i < 32; ++i)
            m = fmaxf(m, fabsf(sm[(kr + i * 16) * 17 + c]));
        red[kr][c] = m;
    }
    __syncthreads();
    if (t < 16) {
        float m = red[0][t];
        #pragma unroll
        for (int r = 1; r < 16; ++r) m = fmaxf(m, red[r][t]);
        float s = __fdiv_rn(127.0f, fmaxf(m, 1e-7f));
        sscale[t] = s;
        const float A_SCALE = 127.0f / 3.0f;
        g_inv[j0 + t] = __fdiv_rn(1.0f, __fmul_rn(A_SCALE, s));
    }
    __syncthreads();

    const int w = t >> 5, lane = t & 31;
    #pragma unroll
    for (int cc = 0; cc < 2; ++cc) {
        int c = w * 2 + cc;
        float s = sscale[c];
        int kb = lane * 16;
        unsigned pk[4];
        #pragma unroll
        for (int i = 0; i < 4; ++i) {
            int q[4];
            #pragma unroll
            for (int jj = 0; jj < 4; ++jj) {
                float v = __fmul_rn(sm[(kb + i * 4 + jj) * 17 + c], s);
                int qi = __float2int_rn(v);
                q[jj] = max(-127, min(127, qi));
            }
            pk[i] = (q[0] & 0xff) | ((q[1] & 0xff) << 8) |
                    ((q[2] & 0xff) << 16) | ((unsigned)(q[3] & 0xff) << 24);
        }
        *(int4*)&g_wq[(size_t)(j0 + c) * KDIM + kb] =
            make_int4(pk[0], pk[1], pk[2], pk[3]);
    }
}

// ---------------------------------------------------------------------------
// Persistent fused quantize-x + int8 MMA GEMM. 3 CTAs/SM, BM=64 tiles,
// strided tile loop, seamless cross-tile W double-buffer via cp.async.
// ---------------------------------------------------------------------------
__device__ __forceinline__ void load_w_async(uint32_t buf_u, int nb, int t) {
    const int8_t* base = g_wq + (size_t)nb * BN * KDIM;
    #pragma unroll
    for (int i = 0; i < 4; ++i) {
        int idx = i * 256 + t;               // 1024 16B-chunks
        int n = idx >> 5, c16 = idx & 31;
        uint32_t dst = buf_u + n * KDIM + ((c16 * 16) ^ ((n & 7) << 4));
        cp_async16(dst, base + n * KDIM + c16 * 16);
    }
    asm volatile("cp.async.commit_group;" ::: "memory");
}

__global__ void __launch_bounds__(256, 3)
gemm_kernel(const float* __restrict__ x, const float* __restrict__ bias,
            float* __restrict__ y) {
    extern __shared__ char smem[];
    int8_t* xs = (int8_t*)(smem + SM_X);
    int8_t* ws = (int8_t*)(smem + SM_W);
    float* sinv  = (float*)(smem + SM_INV);
    float* sbias = (float*)(smem + SM_BIAS);

    const int t = threadIdx.x;
    const uint32_t xs_u = smem_u32(xs);
    const uint32_t ws_u = smem_u32(ws);

    // prime W chunk 0 (buffer 0); overlaps first x-quant
    load_w_async(ws_u, 0, t);

    for (int i = t; i < FDIM; i += 256) {
        sinv[i]  = g_inv[i];
        sbias[i] = bias[i];
    }

    const int warp = t >> 5, lane = t & 31;
    const int wm = warp >> 1, wn = warp & 1;     // 4 M-warps x 2 N-warps
    const int grp = lane >> 2, qid = lane & 3;
    const int mid  = lane >> 3;                  // ldmatrix matrix id
    const int mrow = lane & 7;
    const int bsel = (mid >> 1) << 4;
    const uint32_t gxor = (uint32_t)mrow << 4;

    // A: 16 rows (wm*16..) x 32 k-bytes per ks
    const uint32_t aA = xs_u + (uint32_t)(wm * 16 + (mid & 1) * 8 + mrow) * KDIM;
    // B: 16 n-rows (wn*16..) x 32 k-bytes per ks
    const uint32_t bB = ws_u + (uint32_t)(wn * 16 + (mid & 1) * 8 + mrow) * KDIM;

    const float A_SCALE = 127.0f / 3.0f;

    for (int tile = blockIdx.x; tile < NTILES; tile += GRID) {
        const int r0 = tile * BM;
        __syncthreads();                         // prev tile's MMA done with xs

        // quantize x tile: 64 x 512 fp32 -> int8, XOR-swizzled rows
        #pragma unroll 4
        for (int i = 0; i < 8; ++i) {
            int idx = i * 256 + t;               // 2048 16B-chunks
            int row = idx >> 5, c16 = idx & 31;
            const float4* src = (const float4*)(x + (size_t)(r0 + row) * KDIM + c16 * 16);
            float4 vv[4] = {__ldg(src), __ldg(src + 1), __ldg(src + 2), __ldg(src + 3)};
            int pk[4];
            #pragma unroll
            for (int j = 0; j < 4; ++j) {
                int q0 = max(-127, min(127, __float2int_rn(__fmul_rn(vv[j].x, A_SCALE))));
                int q1 = max(-127, min(127, __float2int_rn(__fmul_rn(vv[j].y, A_SCALE))));
                int q2 = max(-127, min(127, __float2int_rn(__fmul_rn(vv[j].z, A_SCALE))));
                int q3 = max(-127, min(127, __float2int_rn(__fmul_rn(vv[j].w, A_SCALE))));
                pk[j] = (q0 & 0xff) | ((q1 & 0xff) << 8) |
                        ((q2 & 0xff) << 16) | ((unsigned)(q3 & 0xff) << 24);
            }
            *(int4*)&xs[row * KDIM + ((c16 * 16) ^ ((row & 7) << 4))] =
                make_int4(pk[0], pk[1], pk[2], pk[3]);
        }

        float* yr0 = y + (size_t)(r0 + wm * 16 + grp) * FDIM;

        for (int nb = 0; nb < 16; ++nb) {
            // W(nb) was issued a full chunk (or tile-prologue) ago
            asm volatile("cp.async.wait_group 0;" ::: "memory");
            __syncthreads();
            // prefetch next chunk — cross-tile wraps to chunk 0 (tile-invariant)
            load_w_async(ws_u + ((nb + 1) & 1) * WBUF_BYTES, (nb + 1) & 15, t);

            const uint32_t bbase = bB + (nb & 1) * WBUF_BYTES;

            int acc[2][4];
            #pragma unroll
            for (int nt = 0; nt < 2; ++nt)
                #pragma unroll
                for (int r = 0; r < 4; ++r) acc[nt][r] = 0;

            #pragma unroll
            for (int ks = 0; ks < 16; ++ks) {
                const uint32_t off = (uint32_t)(ks * 32 + bsel) ^ gxor;
                unsigned a[4], bb4[4];
                ldsm_x4(aA + off, a[0], a[1], a[2], a[3]);
                // bb4 = {b[0][0], b[1][0], b[0][1], b[1][1]}
                ldsm_x4(bbase + off, bb4[0], bb4[1], bb4[2], bb4[3]);
                asm volatile(
                    "mma.sync.aligned.m16n8k32.row.col.s32.s8.s8.s32 "
                    "{%0,%1,%2,%3},{%4,%5,%6,%7},{%8,%9},{%0,%1,%2,%3};\n"
                    : "+r"(acc[0][0]), "+r"(acc[0][1]), "+r"(acc[0][2]), "+r"(acc[0][3])
                    : "r"(a[0]), "r"(a[1]), "r"(a[2]), "r"(a[3]),
                      "r"(bb4[0]), "r"(bb4[2]));
                asm volatile(
                    "mma.sync.aligned.m16n8k32.row.col.s32.s8.s8.s32 "
                    "{%0,%1,%2,%3},{%4,%5,%6,%7},{%8,%9},{%0,%1,%2,%3};\n"
                    : "+r"(acc[1][0]), "+r"(acc[1][1]), "+r"(acc[1][2]), "+r"(acc[1][3])
                    : "r"(a[0]), "r"(a[1]), "r"(a[2]), "r"(a[3]),
                      "r"(bb4[1]), "r"(bb4[3]));
            }

            // epilogue: dequant + bias, float2 stores
            #pragma unroll
            for (int nt = 0; nt < 2; ++nt) {
                int col = nb * BN + wn * 16 + nt * 8 + qid * 2;
                float i0 = sinv[col], i1 = sinv[col + 1];
                float b0 = sbias[col], b1 = sbias[col + 1];
                float2 v0, v1;
                v0.x = (float)acc[nt][0] * i0 + b0;
                v0.y = (float)acc[nt][1] * i1 + b1;
                v1.x = (float)acc[nt][2] * i0 + b0;
                v1.y = (float)acc[nt][3] * i1 + b1;
                *(float2*)(yr0 + col) = v0;
                *(float2*)(yr0 + 8 * FDIM + col) = v1;
            }
        }
    }
    // drain trailing prefetch before exit
    asm volatile("cp.async.wait_group 0;" ::: "memory");
}

// ---------------------------------------------------------------------------
extern "C" void kernel_launch(void* const* d_in, const int* in_sizes, int n_in,
                              void* d_out, int out_size) {
    const float* x    = (const float*)d_in[0];
    const float* kern = (const float*)d_in[1];
    const float* bias = (const float*)d_in[2];
    float* y = (float*)d_out;

    cudaFuncSetAttribute(gemm_kernel,
                         cudaFuncAttributeMaxDynamicSharedMemorySize, SMEM_TOTAL);

    quant_w_kernel<<<FDIM / 16, 256>>>(kern);
    gemm_kernel<<<GRID, 256, SMEM_TOTAL>>>(x, bias, y);
}

// round 9
// speedup vs baseline: 1.1675x; 1.1363x over previous
#include <cuda_runtime.h>
#include <cstdint>

#define KDIM 512
#define FDIM 512
#define BM   64
#define BN   32                 // 16 chunks per tile
#define NTILES 1024
#define GRID 296                // 2 CTAs x 148 SMs, persistent

// smem layout (bytes)
#define SM_X    0               // 2 x (64 x 512) int8 double buffer, XOR-swizzled
#define XBUF    32768
#define SM_W    65536           // 2 x (32 x 512) int8 double buffer
#define WBUF    16384
#define SM_INV  98304           // 512 floats
#define SM_BIAS 100352          // 512 floats
#define SMEM_TOTAL 102400       // 100 KB -> 2 CTAs/SM

__device__ __align__(16) int8_t g_wq[FDIM * KDIM];   // [F][K]
__device__ float g_inv[FDIM];

__device__ __forceinline__ uint32_t smem_u32(const void* p) {
    uint32_t a;
    asm("{ .reg .u64 t; cvta.to.shared.u64 t, %1; cvt.u32.u64 %0, t; }" : "=r"(a) : "l"(p));
    return a;
}
__device__ __forceinline__ void cp_async16(uint32_t dst, const void* src) {
    asm volatile("cp.async.cg.shared.global [%0], [%1], 16;" :: "r"(dst), "l"(src));
}
__device__ __forceinline__ void ldsm_x4(uint32_t addr, unsigned& r0, unsigned& r1,
                                        unsigned& r2, unsigned& r3) {
    asm volatile("ldmatrix.sync.aligned.m8n8.x4.shared.b16 {%0,%1,%2,%3}, [%4];"
                 : "=r"(r0), "=r"(r1), "=r"(r2), "=r"(r3) : "r"(addr));
}
__device__ __forceinline__ unsigned quant_pack(float4 v) {
    const float A_SCALE = 127.0f / 3.0f;
    int q0 = max(-127, min(127, __float2int_rn(__fmul_rn(v.x, A_SCALE))));
    int q1 = max(-127, min(127, __float2int_rn(__fmul_rn(v.y, A_SCALE))));
    int q2 = max(-127, min(127, __float2int_rn(__fmul_rn(v.z, A_SCALE))));
    int q3 = max(-127, min(127, __float2int_rn(__fmul_rn(v.w, A_SCALE))));
    return (q0 & 0xff) | ((q1 & 0xff) << 8) | ((q2 & 0xff) << 16) |
           ((unsigned)(q3 & 0xff) << 24);
}

// ---------------------------------------------------------------------------
// Weight prequant: 32 blocks x 256 threads, 16 output-cols per block.
// ---------------------------------------------------------------------------
__global__ void quant_w_kernel(const float* __restrict__ kernel) {
    __shared__ float sm[512 * 17];
    __shared__ float red[16][16];
    __shared__ float sscale[16];
    const int j0 = blockIdx.x * 16;
    const int t  = threadIdx.x;

    #pragma unroll 4
    for (int i = 0; i < 32; ++i) {
        int idx = i * 256 + t;
        int k = idx >> 4, c = idx & 15;
        sm[k * 17 + c] = kernel[k * FDIM + j0 + c];
    }
    __syncthreads();
    {
        int c = t & 15, kr = t >> 4;
        float m = 0.f;
        #pragma unroll 8
        for (int i = 0; i < 32; ++i)
            m = fmaxf(m, fabsf(sm[(kr + i * 16) * 17 + c]));
        red[kr][c] = m;
    }
    __syncthreads();
    if (t < 16) {
        float m = red[0][t];
        #pragma unroll
        for (int r = 1; r < 16; ++r) m = fmaxf(m, red[r][t]);
        float s = __fdiv_rn(127.0f, fmaxf(m, 1e-7f));
        sscale[t] = s;
        const float A_SCALE = 127.0f / 3.0f;
        g_inv[j0 + t] = __fdiv_rn(1.0f, __fmul_rn(A_SCALE, s));
    }
    __syncthreads();

    const int w = t >> 5, lane = t & 31;
    #pragma unroll
    for (int cc = 0; cc < 2; ++cc) {
        int c = w * 2 + cc;
        float s = sscale[c];
        int kb = lane * 16;
        unsigned pk[4];
        #pragma unroll
        for (int i = 0; i < 4; ++i) {
            int q[4];
            #pragma unroll
            for (int jj = 0; jj < 4; ++jj) {
                float v = __fmul_rn(sm[(kb + i * 4 + jj) * 17 + c], s);
                int qi = __float2int_rn(v);
                q[jj] = max(-127, min(127, qi));
            }
            pk[i] = (q[0] & 0xff) | ((q[1] & 0xff) << 8) |
                    ((q[2] & 0xff) << 16) | ((unsigned)(q[3] & 0xff) << 24);
        }
        *(int4*)&g_wq[(size_t)(j0 + c) * KDIM + kb] =
            make_int4(pk[0], pk[1], pk[2], pk[3]);
    }
}

// ---------------------------------------------------------------------------
// Persistent fused GEMM: next-tile x load+quant pipelined under current-tile
// MMA chunks (double-buffered xs), W double-buffered via cp.async. 2 CTAs/SM.
// ---------------------------------------------------------------------------
__device__ __forceinline__ void load_w_async(uint32_t buf_u, int nb, int t) {
    const int8_t* base = g_wq + (size_t)nb * BN * KDIM;
    #pragma unroll
    for (int i = 0; i < 4; ++i) {
        int idx = i * 256 + t;               // 1024 16B-chunks
        int n = idx >> 5, c16 = idx & 31;
        uint32_t dst = buf_u + n * KDIM + ((c16 * 16) ^ ((n & 7) << 4));
        cp_async16(dst, base + n * KDIM + c16 * 16);
    }
    asm volatile("cp.async.commit_group;" ::: "memory");
}

__global__ void __launch_bounds__(256, 2)
gemm_kernel(const float* __restrict__ x, const float* __restrict__ bias,
            float* __restrict__ y) {
    extern __shared__ char smem[];
    int8_t* xs = (int8_t*)(smem + SM_X);
    float* sinv  = (float*)(smem + SM_INV);
    float* sbias = (float*)(smem + SM_BIAS);

    const int t = threadIdx.x;
    const uint32_t xs_u = smem_u32(xs);
    const uint32_t ws_u = smem_u32(smem + SM_W);

    // prime W chunk 0 (buffer 0); overlaps tile-0 x-quant
    load_w_async(ws_u, 0, t);

    for (int i = t; i < FDIM; i += 256) {
        sinv[i]  = g_inv[i];
        sbias[i] = bias[i];
    }

    // tile-0 x-quant into xs buffer 0 (only DRAM-exposed quant phase)
    {
        const int r0 = blockIdx.x * BM;
        #pragma unroll 4
        for (int i = 0; i < 8; ++i) {
            int idx = i * 256 + t;
            int row = idx >> 5, c16 = idx & 31;
            const float4* src = (const float4*)(x + (size_t)(r0 + row) * KDIM + c16 * 16);
            unsigned pk[4];
            #pragma unroll
            for (int j = 0; j < 4; ++j) pk[j] = quant_pack(__ldg(src + j));
            *(uint4*)&xs[row * KDIM + ((c16 * 16) ^ ((row & 7) << 4))] =
                make_uint4(pk[0], pk[1], pk[2], pk[3]);
        }
    }

    const int warp = t >> 5, lane = t & 31;
    const int wm = warp >> 1, wn = warp & 1;     // 4 M-warps x 2 N-warps
    const int grp = lane >> 2, qid = lane & 3;
    const int mid  = lane >> 3;
    const int mrow = lane & 7;
    const int bsel = (mid >> 1) << 4;
    const uint32_t gxor = (uint32_t)mrow << 4;

    const uint32_t aoff = (uint32_t)(wm * 16 + (mid & 1) * 8 + mrow) * KDIM;
    const uint32_t bB   = ws_u + (uint32_t)(wn * 16 + (mid & 1) * 8 + mrow) * KDIM;

    int bx = 0;
    for (int tile = blockIdx.x; tile < NTILES; tile += GRID, bx ^= 1) {
        const int r0 = tile * BM;
        const int nxt_r0 = (tile + GRID) * BM;
        const bool pf = (tile + GRID) < NTILES;
        const uint32_t xcur = xs_u + bx * XBUF;
        int8_t* xnext = xs + (bx ^ 1) * XBUF;
        const uint32_t aA = xcur + aoff;
        float* yr0 = y + (size_t)(r0 + wm * 16 + grp) * FDIM;

        for (int nb = 0; nb < 16; ++nb) {
            // W(nb) committed one chunk ago
            asm volatile("cp.async.wait_group 0;" ::: "memory");
            __syncthreads();
            load_w_async(ws_u + ((nb + 1) & 1) * WBUF, (nb + 1) & 15, t);

            // issue next-tile x loads early (latency hides under MMA below)
            float4 va, vb;
            int xrow_a = 0, xc4_a = 0, xrow_b = 0, xc4_b = 0;
            if (pf) {
                int ia = nb * 512 + t;             // float4 index in 64x128 grid
                int ib = ia + 256;
                xrow_a = ia >> 7; xc4_a = ia & 127;
                xrow_b = ib >> 7; xc4_b = ib & 127;
                va = __ldg((const float4*)(x + (size_t)(nxt_r0 + xrow_a) * KDIM) + xc4_a);
                vb = __ldg((const float4*)(x + (size_t)(nxt_r0 + xrow_b) * KDIM) + xc4_b);
            }

            const uint32_t bbase = bB + (nb & 1) * WBUF;

            int acc[2][4];
            #pragma unroll
            for (int nt = 0; nt < 2; ++nt)
                #pragma unroll
                for (int r = 0; r < 4; ++r) acc[nt][r] = 0;

            #pragma unroll
            for (int ks = 0; ks < 16; ++ks) {
                const uint32_t off = (uint32_t)(ks * 32 + bsel) ^ gxor;
                unsigned a[4], bb4[4];
                ldsm_x4(aA + off, a[0], a[1], a[2], a[3]);
                ldsm_x4(bbase + off, bb4[0], bb4[1], bb4[2], bb4[3]);
                asm volatile(
                    "mma.sync.aligned.m16n8k32.row.col.s32.s8.s8.s32 "
                    "{%0,%1,%2,%3},{%4,%5,%6,%7},{%8,%9},{%0,%1,%2,%3};\n"
                    : "+r"(acc[0][0]), "+r"(acc[0][1]), "+r"(acc[0][2]), "+r"(acc[0][3])
                    : "r"(a[0]), "r"(a[1]), "r"(a[2]), "r"(a[3]),
                      "r"(bb4[0]), "r"(bb4[2]));
                asm volatile(
                    "mma.sync.aligned.m16n8k32.row.col.s32.s8.s8.s32 "
                    "{%0,%1,%2,%3},{%4,%5,%6,%7},{%8,%9},{%0,%1,%2,%3};\n"
                    : "+r"(acc[1][0]), "+r"(acc[1][1]), "+r"(acc[1][2]), "+r"(acc[1][3])
                    : "r"(a[0]), "r"(a[1]), "r"(a[2]), "r"(a[3]),
                      "r"(bb4[1]), "r"(bb4[3]));
            }

            // complete the x prefetch: quantize + store to the other x buffer
            if (pf) {
                *(unsigned*)&xnext[xrow_a * KDIM +
                    (((xc4_a * 4) & ~15) ^ ((xrow_a & 7) << 4)) + ((xc4_a & 3) * 4)] =
                    quant_pack(va);
                *(unsigned*)&xnext[xrow_b * KDIM +
                    (((xc4_b * 4) & ~15) ^ ((xrow_b & 7) << 4)) + ((xc4_b & 3) * 4)] =
                    quant_pack(vb);
            }

            // epilogue: dequant + bias, float2 stores
            #pragma unroll
            for (int nt = 0; nt < 2; ++nt) {
                int col = nb * BN + wn * 16 + nt * 8 + qid * 2;
                float i0 = sinv[col], i1 = sinv[col + 1];
                float b0 = sbias[col], b1 = sbias[col + 1];
                float2 v0, v1;
                v0.x = (float)acc[nt][0] * i0 + b0;
                v0.y = (float)acc[nt][1] * i1 + b1;
                v1.x = (float)acc[nt][2] * i0 + b0;
                v1.y = (float)acc[nt][3] * i1 + b1;
                *(float2*)(yr0 + col) = v0;
                *(float2*)(yr0 + 8 * FDIM + col) = v1;
            }
        }
    }
    asm volatile("cp.async.wait_group 0;" ::: "memory");
}

// ---------------------------------------------------------------------------
extern "C" void kernel_launch(void* const* d_in, const int* in_sizes, int n_in,
                              void* d_out, int out_size) {
    const float* x    = (const float*)d_in[0];
    const float* kern = (const float*)d_in[1];
    const float* bias = (const float*)d_in[2];
    float* y = (float*)d_out;

    cudaFuncSetAttribute(gemm_kernel,
                         cudaFuncAttributeMaxDynamicSharedMemorySize, SMEM_TOTAL);

    quant_w_kernel<<<FDIM / 16, 256>>>(kern);
    gemm_kernel<<<GRID, 256, SMEM_TOTAL>>>(x, bias, y);
}